// round 8
// baseline (speedup 1.0000x reference)
#include <cuda_runtime.h>
#include <cstdint>

// EFLSTM via int8 Karatsuba mma.sync (m16n8k32.s8) — exact 14-bit fixed-point products.
// q = 128*a1 + a2  (|a1|<=64, |a2|<=64, asum=a1+a2 in int8)
// q_a*q_b = 16256*P1 + 128*P2 - 127*P3  with P1=a1b1, P2=asum*bsum, P3=a2b2 (exact).
//   phase 1: xg = x @ Wih^T + bias  (parallel, fp32 out, 1GB scratch)
//   phase 2: 256 sequential steps: gates = h @ Whh^T + xg; fused LSTM cell update
//   phase 3: MLP head
// Gate cols permuted n = j*4 + band. All operand images chunk-major, pre-swizzled,
// staged via 1D cp.async.bulk (6 bulk ops per K=128 chunk).

#define BB 256
#define TT 256
#define D_TXT 300
#define D_AUD 74
#define D_VIS 35
#define DD 409
#define HH 1024
#define G4 4096
#define NCELL 512
#define HCK 8   // K=1024 -> 8 chunks of 128
#define XCK 4   // K=512 (padded 409) -> 4 chunks of 128

// ---------------- device scratch ----------------
__device__ __align__(128) int8_t g_hq[2][3][HCK * 256 * 128];            // h images
__device__ __align__(128) int8_t g_wq[3][(size_t)HCK * G4 * 128];        // Whh images
__device__ __align__(128) int8_t g_wiq[3][(size_t)XCK * G4 * 128];       // Wih images
__device__ __align__(128) int8_t g_xq[3][(size_t)TT * XCK * BB * 128];   // x images
__device__ float g_c[BB * HH];
__device__ float g_hf[BB * HH];
__device__ float g_bsum[G4];
__device__ float g_xg[(size_t)TT * BB * G4];
__device__ int g_maxbits[3];                 // |Whh|, |Wih|, |x|
__device__ float g_Sw, g_Swi, g_Sx, g_inv_step, g_inv_xg;

// ---------------- helpers ----------------
__device__ __forceinline__ uint32_t s2u(const void* p) {
    uint32_t a;
    asm("{ .reg .u64 t; cvta.to.shared.u64 t, %1; cvt.u32.u64 %0, t; }" : "=r"(a) : "l"(p));
    return a;
}
__device__ __forceinline__ int swz128(int row, int col) {  // col in bytes 0..127
    return (((col >> 4) ^ (row & 7)) << 4) | (col & 15);
}
__device__ __forceinline__ void quant3(float v, float S, int8_t* p1, int8_t* p2, int8_t* ps) {
    int iq = __float2int_rn(v * S);          // |iq| <= 8128 by scale choice
    int A1 = (iq + 64) >> 7;
    int A2 = iq - (A1 << 7);
    *p1 = (int8_t)A1; *p2 = (int8_t)A2; *ps = (int8_t)(A1 + A2);
}
#define MBINIT(a, c) asm volatile("mbarrier.init.shared.b64 [%0], %1;" ::"r"(a), "r"(c) : "memory")
#define MBWAIT(a, ph) do {                                                                  \
    uint32_t _d;                                                                            \
    asm volatile("{\n .reg .pred p;\n mbarrier.try_wait.parity.acquire.cta.shared::cta.b64 p,[%1],%2;\n selp.b32 %0,1,0,p;\n}" \
                 : "=r"(_d) : "r"(a), "r"(ph) : "memory");                                  \
    while (!_d) {                                                                           \
        asm volatile("{\n .reg .pred p;\n mbarrier.try_wait.parity.acquire.cta.shared::cta.b64 p,[%1],%2,0x989680;\n selp.b32 %0,1,0,p;\n}" \
                     : "=r"(_d) : "r"(a), "r"(ph) : "memory");                              \
    }                                                                                       \
} while (0)
#define MBEXPECT(bar, bytes) \
    asm volatile("mbarrier.arrive.expect_tx.shared.b64 _, [%0], %1;" ::"r"(bar), "r"(bytes) : "memory")
#define BULK(dst, src, bytes, bar)                                                          \
    asm volatile("cp.async.bulk.shared::cluster.global.mbarrier::complete_tx::bytes "       \
                 "[%0], [%1], %2, [%3];"                                                    \
                 ::"r"(dst), "l"((const void*)(src)), "r"(bytes), "r"(bar) : "memory")
#define LDSM4(r, a)                                                                         \
    asm volatile("ldmatrix.sync.aligned.m8n8.x4.shared.b16 {%0,%1,%2,%3}, [%4];"            \
                 : "=r"((r)[0]), "=r"((r)[1]), "=r"((r)[2]), "=r"((r)[3]) : "r"(a))
#define IMMA(acc, a, b0, b1)                                                                \
    asm volatile("mma.sync.aligned.m16n8k32.row.col.s32.s8.s8.s32 "                         \
                 "{%0,%1,%2,%3}, {%4,%5,%6,%7}, {%8,%9}, {%0,%1,%2,%3};"                    \
                 : "+r"((acc)[0]), "+r"((acc)[1]), "+r"((acc)[2]), "+r"((acc)[3])           \
                 : "r"((a)[0]), "r"((a)[1]), "r"((a)[2]), "r"((a)[3]), "r"(b0), "r"(b1))

// one K=128 chunk (4 k32 steps), 3 Karatsuba passes. Warp tile (TM*16) x 32.
// smem images: row-major [rows][128 int8], swizzle off ^ ((row&7)<<4) in 16B units.
template <int TM>
__device__ __forceinline__ void i8_chunk(
    uint32_t sA1, uint32_t sA2, uint32_t sAs,
    uint32_t sB1, uint32_t sB2, uint32_t sBs,
    int mbase, int nbase, int lane,
    int p1[TM][4][4], int p2[TM][4][4], int p3[TM][4][4])
{
#pragma unroll
    for (int kk = 0; kk < 4; kk++) {
        uint32_t b1[2][4], b2[2][4], bs[2][4];
#pragma unroll
        for (int tn = 0; tn < 2; tn++) {
            const uint32_t g = (uint32_t)(lane >> 3);
            const uint32_t row = (uint32_t)(nbase + tn * 16) + ((g >> 1) << 3) + (uint32_t)(lane & 7);
            const uint32_t kb = (uint32_t)(kk * 32) + ((g & 1u) << 4);
            const uint32_t off = row * 128u + (kb ^ ((row & 7u) << 4));
            LDSM4(b1[tn], sB1 + off);
            LDSM4(b2[tn], sB2 + off);
            LDSM4(bs[tn], sBs + off);
        }
#pragma unroll
        for (int tm = 0; tm < TM; tm++) {
            uint32_t a1[4], a2[4], as[4];
            const uint32_t row = (uint32_t)(mbase + tm * 16 + (lane & 15));
            const uint32_t kb = (uint32_t)(kk * 32) + ((uint32_t)(lane >> 4) << 4);
            const uint32_t off = row * 128u + (kb ^ ((row & 7u) << 4));
            LDSM4(a1, sA1 + off);
            LDSM4(a2, sA2 + off);
            LDSM4(as, sAs + off);
#pragma unroll
            for (int tn = 0; tn < 4; tn++)
                IMMA(p1[tm][tn], a1, b1[tn >> 1][(tn & 1) * 2], b1[tn >> 1][(tn & 1) * 2 + 1]);
#pragma unroll
            for (int tn = 0; tn < 4; tn++)
                IMMA(p2[tm][tn], as, bs[tn >> 1][(tn & 1) * 2], bs[tn >> 1][(tn & 1) * 2 + 1]);
#pragma unroll
            for (int tn = 0; tn < 4; tn++)
                IMMA(p3[tm][tn], a2, b2[tn >> 1][(tn & 1) * 2], b2[tn >> 1][(tn & 1) * 2 + 1]);
        }
    }
}

// combine exact product and store to smem staging
template <int TM>
__device__ __forceinline__ void store_comb(float* sacc, int pitch,
                                           int p1[TM][4][4], int p2[TM][4][4], int p3[TM][4][4],
                                           int mbase, int nbase, int lane) {
#pragma unroll
    for (int tm = 0; tm < TM; tm++)
#pragma unroll
        for (int tn = 0; tn < 4; tn++) {
            float v[4];
#pragma unroll
            for (int e = 0; e < 4; e++)
                v[e] = 16256.f * (float)p1[tm][tn][e] + 128.f * (float)p2[tm][tn][e]
                       - 127.f * (float)p3[tm][tn][e];
            const int r = mbase + tm * 16 + (lane >> 2);
            const int cc = nbase + tn * 8 + (lane & 3) * 2;
            *(float2*)&sacc[r * pitch + cc] = make_float2(v[0], v[1]);
            *(float2*)&sacc[(r + 8) * pitch + cc] = make_float2(v[2], v[3]);
        }
}

// ---------------- prep ----------------
__global__ void init_kernel() {
    int i = blockIdx.x * blockDim.x + threadIdx.x;
    if (i < BB * HH) g_c[i] = 0.f;
    if (i < 3 * HCK * 256 * 128 / 4) ((uint32_t*)&g_hq[0][0][0])[i] = 0u;
    if (i == 0) { g_maxbits[0] = 0; g_maxbits[1] = 0; g_maxbits[2] = 0; }
}

__global__ void maxabs_kernel(const float* __restrict__ p, size_t n, int idx) {
    __shared__ float red[256];
    float m = 0.f;
    for (size_t i = (size_t)blockIdx.x * 256 + threadIdx.x; i < n; i += (size_t)gridDim.x * 256)
        m = fmaxf(m, fabsf(p[i]));
    red[threadIdx.x] = m;
    __syncthreads();
    for (int s = 128; s > 0; s >>= 1) {
        if (threadIdx.x < s) red[threadIdx.x] = fmaxf(red[threadIdx.x], red[threadIdx.x + s]);
        __syncthreads();
    }
    if (threadIdx.x == 0) atomicMax(&g_maxbits[idx], __float_as_int(red[0]));
}

__global__ void scale_kernel() {
    const float mw  = fmaxf(__int_as_float(g_maxbits[0]), 1e-20f);
    const float mwi = fmaxf(__int_as_float(g_maxbits[1]), 1e-20f);
    const float mx  = fmaxf(__int_as_float(g_maxbits[2]), 1e-20f);
    g_Sw = 8128.f / mw;
    g_Swi = 8128.f / mwi;
    g_Sx = 8128.f / mx;
    g_inv_step = 1.f / (8128.f * g_Sw);
    g_inv_xg = 1.f / (g_Sx * g_Swi);
}

__global__ void prep_w(const float* __restrict__ Whh, const float* __restrict__ bih,
                       const float* __restrict__ bhh) {
    size_t i = (size_t)blockIdx.x * 256 + threadIdx.x;
    if (i >= (size_t)G4 * HH) return;
    int n = (int)(i / HH), k = (int)(i % HH);
    int gc = (n & 3) * HH + (n >> 2);
    float w = Whh[(size_t)gc * HH + k];
    size_t oi = ((size_t)(k >> 7) * G4 + n) * 128 + swz128(n, k & 127);
    quant3(w, g_Sw, &g_wq[0][oi], &g_wq[1][oi], &g_wq[2][oi]);
    if (k == 0) g_bsum[n] = bih[gc] + bhh[gc];
}

__global__ void prep_wi(const float* __restrict__ Wih) {
    size_t i = (size_t)blockIdx.x * 256 + threadIdx.x;
    if (i >= (size_t)G4 * 512) return;
    int n = (int)(i / 512), k = (int)(i % 512);
    int gc = (n & 3) * HH + (n >> 2);
    float w = (k < DD) ? Wih[(size_t)gc * DD + k] : 0.f;
    size_t oi = ((size_t)(k >> 7) * G4 + n) * 128 + swz128(n, k & 127);
    quant3(w, g_Swi, &g_wiq[0][oi], &g_wiq[1][oi], &g_wiq[2][oi]);
}

__global__ void prep_x(const float* __restrict__ xt, const float* __restrict__ xa,
                       const float* __restrict__ xv) {
    size_t i = (size_t)blockIdx.x * 256 + threadIdx.x;
    if (i >= (size_t)TT * BB * 512) return;
    int d = (int)(i % 512);
    size_t tb = i / 512;
    int b = (int)(tb % BB), t = (int)(tb / BB);
    float v = 0.f;
    if (d < D_TXT)              v = xt[((size_t)b * TT + t) * D_TXT + d];
    else if (d < D_TXT + D_AUD) v = xa[((size_t)b * TT + t) * D_AUD + (d - D_TXT)];
    else if (d < DD)            v = xv[((size_t)b * TT + t) * D_VIS + (d - D_TXT - D_AUD)];
    size_t oi = (((size_t)t * XCK + (d >> 7)) * BB + b) * 128 + swz128(b, d & 127);
    quant3(v, g_Sx, &g_xq[0][oi], &g_xq[1][oi], &g_xq[2][oi]);
}

// ---------------- xg GEMM: xg = x @ Wih^T + bias ----------------
// 128(m=batch rows at fixed t) x 64(n) tiles, grid (64, 512). 4 chunks, 2 stages x 72KB.
// stage: A1 0 | A2 16K | As 32K | B1 48K | B2 56K | Bs 64K
#define PITCH 68
#define STG 73728u
__global__ __launch_bounds__(256, 1) void xg_kernel() {
    extern __shared__ __align__(128) char dsm[];
    __shared__ __align__(8) uint64_t s_mbar[2];
    const int tid = threadIdx.x;
    const int lane = tid & 31, wid = tid >> 5;
    const int wy = wid >> 1, wx = wid & 1;
    const int n0 = blockIdx.x * 64;
    const int t = blockIdx.y >> 1, b0 = (blockIdx.y & 1) * 128;
    const uint32_t sb = s2u(dsm);
    const uint32_t mb = s2u(s_mbar);

    if (tid == 0) { MBINIT(mb, 1); MBINIT(mb + 8, 1); }
    __syncthreads();

    auto issue = [&](int ck) {
        const uint32_t st = sb + (uint32_t)(ck & 1) * STG;
        const uint32_t bar = mb + (uint32_t)(ck & 1) * 8;
        MBEXPECT(bar, 73728u);
        const size_t ab = (((size_t)t * XCK + ck) * BB + b0) * 128;
        BULK(st,           &g_xq[0][ab], 16384u, bar);
        BULK(st + 16384u,  &g_xq[1][ab], 16384u, bar);
        BULK(st + 32768u,  &g_xq[2][ab], 16384u, bar);
        const size_t bb = ((size_t)ck * G4 + n0) * 128;
        BULK(st + 49152u,  &g_wiq[0][bb], 8192u, bar);
        BULK(st + 57344u,  &g_wiq[1][bb], 8192u, bar);
        BULK(st + 65536u,  &g_wiq[2][bb], 8192u, bar);
    };
    if (tid == 0) { issue(0); issue(1); }

    int p1[2][4][4], p2[2][4][4], p3[2][4][4];
#pragma unroll
    for (int i = 0; i < 2; i++)
#pragma unroll
        for (int j = 0; j < 4; j++)
#pragma unroll
            for (int k = 0; k < 4; k++) { p1[i][j][k] = 0; p2[i][j][k] = 0; p3[i][j][k] = 0; }

#pragma unroll 1
    for (int ck = 0; ck < XCK; ck++) {
        MBWAIT(mb + (ck & 1) * 8, (ck >> 1) & 1);
        const uint32_t st = sb + (uint32_t)(ck & 1) * STG;
        i8_chunk<2>(st, st + 16384u, st + 32768u, st + 49152u, st + 57344u, st + 65536u,
                    wy * 32, wx * 32, lane, p1, p2, p3);
        __syncthreads();
        if (ck + 2 < XCK && tid == 0) issue(ck + 2);
    }

    float* sacc = (float*)dsm;
    store_comb<2>(sacc, PITCH, p1, p2, p3, wy * 32, wx * 32, lane);
    __syncthreads();
    const float inv = g_inv_xg;
    for (int e = tid; e < 128 * 16; e += 256) {
        const int m = e >> 4, q = e & 15;
        float4 g = *(float4*)&sacc[m * PITCH + q * 4];
        const float4 bs = *(const float4*)&g_bsum[n0 + q * 4];
        g.x = g.x * inv + bs.x; g.y = g.y * inv + bs.y;
        g.z = g.z * inv + bs.z; g.w = g.w * inv + bs.w;
        *(float4*)&g_xg[((size_t)t * BB + b0 + m) * G4 + n0 + q * 4] = g;
    }
}

// ---------------- LSTM step ----------------
// 128(m) x 64(n) tiles, grid (64, 2) = 128 CTAs. 8 chunks, 2 stages x 72KB.
__global__ __launch_bounds__(256, 1) void step_kernel(int t) {
    extern __shared__ __align__(128) char dsm[];
    __shared__ __align__(8) uint64_t s_mbar[2];
    const int tid = threadIdx.x;
    const int lane = tid & 31, wid = tid >> 5;
    const int wy = wid >> 1, wx = wid & 1;
    const int m0 = blockIdx.y * 128, n0 = blockIdx.x * 64;
    const int rb = t & 1, wb = rb ^ 1;
    const uint32_t sb = s2u(dsm);
    const uint32_t mb = s2u(s_mbar);

    if (tid == 0) { MBINIT(mb, 1); MBINIT(mb + 8, 1); }
    __syncthreads();

    auto issue = [&](int ck) {
        const uint32_t st = sb + (uint32_t)(ck & 1) * STG;
        const uint32_t bar = mb + (uint32_t)(ck & 1) * 8;
        MBEXPECT(bar, 73728u);
        const size_t ab = ((size_t)ck * 256 + m0) * 128;
        BULK(st,           &g_hq[rb][0][ab], 16384u, bar);
        BULK(st + 16384u,  &g_hq[rb][1][ab], 16384u, bar);
        BULK(st + 32768u,  &g_hq[rb][2][ab], 16384u, bar);
        const size_t bb = ((size_t)ck * G4 + n0) * 128;
        BULK(st + 49152u,  &g_wq[0][bb], 8192u, bar);
        BULK(st + 57344u,  &g_wq[1][bb], 8192u, bar);
        BULK(st + 65536u,  &g_wq[2][bb], 8192u, bar);
    };
    if (tid == 0) { issue(0); issue(1); }

    int p1[2][4][4], p2[2][4][4], p3[2][4][4];
#pragma unroll
    for (int i = 0; i < 2; i++)
#pragma unroll
        for (int j = 0; j < 4; j++)
#pragma unroll
            for (int k = 0; k < 4; k++) { p1[i][j][k] = 0; p2[i][j][k] = 0; p3[i][j][k] = 0; }

#pragma unroll 1
    for (int ck = 0; ck < HCK; ck++) {
        MBWAIT(mb + (ck & 1) * 8, (ck >> 1) & 1);
        const uint32_t st = sb + (uint32_t)(ck & 1) * STG;
        i8_chunk<2>(st, st + 16384u, st + 32768u, st + 49152u, st + 57344u, st + 65536u,
                    wy * 32, wx * 32, lane, p1, p2, p3);
        __syncthreads();
        if (ck + 2 < HCK && tid == 0) issue(ck + 2);
    }

    float* sacc = (float*)dsm;
    store_comb<2>(sacc, PITCH, p1, p2, p3, wy * 32, wx * 32, lane);
    __syncthreads();

    const float inv = g_inv_step;
    for (int e = tid; e < 128 * 16; e += 256) {
        const int mloc = e >> 4, q = e & 15;
        const int gm = m0 + mloc;
        const float4 g = *(float4*)&sacc[mloc * PITCH + q * 4];
        const float4 xgv = *(const float4*)&g_xg[((size_t)t * BB + gm) * G4 + n0 + q * 4];
        const float gi = g.x * inv + xgv.x;
        const float gf = g.y * inv + xgv.y;
        const float gg = g.z * inv + xgv.z;
        const float go = g.w * inv + xgv.w;
        const float si = 1.f / (1.f + __expf(-gi));
        const float sf = 1.f / (1.f + __expf(-gf));
        const float tg = tanhf(gg);
        const float so = 1.f / (1.f + __expf(-go));
        const int j = (n0 >> 2) + q;
        const size_t cidx = (size_t)gm * HH + j;
        const float c = sf * g_c[cidx] + si * tg;
        g_c[cidx] = c;
        const float h = so * tanhf(c);
        // quantize h and write packed swizzled images for next step
        const size_t hidx = ((size_t)(j >> 7) * 256 + gm) * 128 + swz128(gm, j & 127);
        quant3(h, 8128.f, &g_hq[wb][0][hidx], &g_hq[wb][1][hidx], &g_hq[wb][2][hidx]);
        if (t == TT - 1) g_hf[cidx] = h;
    }
}

// ---------------- MLP head ----------------
__global__ __launch_bounds__(256) void mlp_kernel(
    const float* __restrict__ W1, const float* __restrict__ b1,
    const float* __restrict__ W2, const float* __restrict__ b2,
    float* __restrict__ out) {
    __shared__ float hrow[HH];
    __shared__ float red[256];
    const int b = blockIdx.x;
    const int tid = threadIdx.x;

    const float* __restrict__ h = &g_hf[(size_t)b * HH];
    for (int k = tid; k < HH; k += 256) hrow[k] = h[k];
    __syncthreads();

    float sum = 0.f;
    for (int cc = tid; cc < NCELL; cc += 256) {
        const float* __restrict__ w = &W1[(size_t)cc * HH];
        float acc = b1[cc];
        for (int k = 0; k < HH; k += 4) {
            const float4 wv = *(const float4*)&w[k];
            acc += hrow[k] * wv.x + hrow[k + 1] * wv.y + hrow[k + 2] * wv.z + hrow[k + 3] * wv.w;
        }
        sum += fmaxf(acc, 0.f) * W2[cc];
    }
    red[tid] = sum;
    __syncthreads();
    for (int s = 128; s > 0; s >>= 1) {
        if (tid < s) red[tid] += red[tid + s];
        __syncthreads();
    }
    if (tid == 0) out[b] = red[0] + b2[0];
}

// ---------------- launch ----------------
extern "C" void kernel_launch(void* const* d_in, const int* in_sizes, int n_in,
                              void* d_out, int out_size) {
    const float* xt  = (const float*)d_in[0];
    const float* xa  = (const float*)d_in[1];
    const float* xv  = (const float*)d_in[2];
    const float* Wih = (const float*)d_in[3];
    const float* Whh = (const float*)d_in[4];
    const float* bih = (const float*)d_in[5];
    const float* bhh = (const float*)d_in[6];
    const float* W1  = (const float*)d_in[7];
    const float* b1  = (const float*)d_in[8];
    const float* W2  = (const float*)d_in[9];
    const float* b2  = (const float*)d_in[10];
    float* out = (float*)d_out;

    const int DSM = 2 * 73728;   // 144KB
    cudaFuncSetAttribute(xg_kernel, cudaFuncAttributeMaxDynamicSharedMemorySize, DSM);
    cudaFuncSetAttribute(step_kernel, cudaFuncAttributeMaxDynamicSharedMemorySize, DSM);

    init_kernel<<<(BB * HH + 255) / 256, 256>>>();
    maxabs_kernel<<<1024, 256>>>(Whh, (size_t)G4 * HH, 0);
    maxabs_kernel<<<1024, 256>>>(Wih, (size_t)G4 * DD, 1);
    maxabs_kernel<<<1024, 256>>>(xt, (size_t)BB * TT * D_TXT, 2);
    maxabs_kernel<<<1024, 256>>>(xa, (size_t)BB * TT * D_AUD, 2);
    maxabs_kernel<<<1024, 256>>>(xv, (size_t)BB * TT * D_VIS, 2);
    scale_kernel<<<1, 1>>>();
    prep_w<<<(int)(((size_t)G4 * HH + 255) / 256), 256>>>(Whh, bih, bhh);
    prep_wi<<<(int)(((size_t)G4 * 512 + 255) / 256), 256>>>(Wih);
    prep_x<<<(int)(((size_t)TT * BB * 512 + 255) / 256), 256>>>(xt, xa, xv);
    xg_kernel<<<dim3(64, 512), 256, DSM>>>();
    for (int t = 0; t < TT; t++)
        step_kernel<<<dim3(64, 2), 256, DSM>>>(t);
    mlp_kernel<<<BB, 256>>>(W1, b1, W2, b2, out);
}

// round 9
// speedup vs baseline: 2.6333x; 2.6333x over previous
#include <cuda_runtime.h>
#include <cuda_bf16.h>
#include <cstdint>

// EFLSTM via warp-level bf16x3 mma.sync + cp.async.bulk staging + warp-specialized
// producer (full/empty mbarrier rings, no per-chunk __syncthreads).
// Packed gmem layouts are chunk-major and PRE-SWIZZLED (exact smem image).
//   phase 1: xg = x @ Wih^T + bias  (parallel GEMM, fp32, 1GB scratch)
//   phase 2: 256 sequential steps: gates = h @ Whh^T + xg; fused LSTM cell update
//   phase 3: MLP head
// Gate cols permuted n = j*4 + band. bf16x3: Ah*Bh + Al*Bh + Ah*Bl, fp32 accum.

#define BB 256
#define TT 256
#define D_TXT 300
#define D_AUD 74
#define D_VIS 35
#define DD 409
#define HH 1024
#define G4 4096
#define XP 448
#define NCELL 512

// ---------------- device scratch ----------------
__device__ __nv_bfloat16 g_hp[2][2][16 * 256 * 64];          // h images [buf][hi/lo]
__device__ float g_c[BB * HH];
__device__ float g_hf[BB * HH];
__device__ __nv_bfloat16 g_wpk[2][(size_t)16 * G4 * 64];     // Whh images
__device__ __nv_bfloat16 g_wipk[2][(size_t)7 * G4 * 64];     // Wih images
__device__ __nv_bfloat16 g_xpk[2][(size_t)TT * 7 * BB * 64]; // x images
__device__ float g_bsum[G4];
__device__ float g_xg[(size_t)TT * BB * G4];

// ---------------- helpers ----------------
__device__ __forceinline__ uint32_t s2u(const void* p) {
    uint32_t a;
    asm("{ .reg .u64 t; cvta.to.shared.u64 t, %1; cvt.u32.u64 %0, t; }" : "=r"(a) : "l"(p));
    return a;
}
#define MBINIT(a, c) asm volatile("mbarrier.init.shared.b64 [%0], %1;" ::"r"(a), "r"(c) : "memory")
#define MBARRIVE(a) asm volatile("mbarrier.arrive.shared.b64 _, [%0];" ::"r"(a) : "memory")
#define MBWAIT(a, ph) do {                                                                  \
    uint32_t _d;                                                                            \
    asm volatile("{\n .reg .pred p;\n mbarrier.try_wait.parity.acquire.cta.shared::cta.b64 p,[%1],%2;\n selp.b32 %0,1,0,p;\n}" \
                 : "=r"(_d) : "r"(a), "r"(ph) : "memory");                                  \
    while (!_d) {                                                                           \
        asm volatile("{\n .reg .pred p;\n mbarrier.try_wait.parity.acquire.cta.shared::cta.b64 p,[%1],%2,0x989680;\n selp.b32 %0,1,0,p;\n}" \
                     : "=r"(_d) : "r"(a), "r"(ph) : "memory");                              \
    }                                                                                       \
} while (0)
#define MBEXPECT(bar, bytes) \
    asm volatile("mbarrier.arrive.expect_tx.shared.b64 _, [%0], %1;" ::"r"(bar), "r"(bytes) : "memory")
#define BULK(dst, src, bytes, bar)                                                          \
    asm volatile("cp.async.bulk.shared::cluster.global.mbarrier::complete_tx::bytes "       \
                 "[%0], [%1], %2, [%3];"                                                    \
                 ::"r"(dst), "l"((const void*)(src)), "r"(bytes), "r"(bar) : "memory")
#define BARC() asm volatile("bar.sync 1, 256;" ::: "memory")
#define LDSM4(r, a)                                                                         \
    asm volatile("ldmatrix.sync.aligned.m8n8.x4.shared.b16 {%0,%1,%2,%3}, [%4];"            \
                 : "=r"((r)[0]), "=r"((r)[1]), "=r"((r)[2]), "=r"((r)[3]) : "r"(a))
#define MMA(acc, a, b0, b1)                                                                 \
    asm volatile("mma.sync.aligned.m16n8k16.row.col.f32.bf16.bf16.f32 "                     \
                 "{%0,%1,%2,%3}, {%4,%5,%6,%7}, {%8,%9}, {%0,%1,%2,%3};"                    \
                 : "+f"((acc)[0]), "+f"((acc)[1]), "+f"((acc)[2]), "+f"((acc)[3])           \
                 : "r"((a)[0]), "r"((a)[1]), "r"((a)[2]), "r"((a)[3]), "r"(b0), "r"(b1))

// fused 3-term compute over one K=64 chunk. Warp tile (TM*16) x 32.
// smem tiles: row-major [rows][64 bf16], 128B/row, swizzle off ^ ((row&7)<<4).
template <int TM>
__device__ __forceinline__ void fused3_chunk(
    uint32_t sAh, uint32_t sAl, uint32_t sBh, uint32_t sBl,
    int mbase, int nbase, int lane, float acc[TM][4][4])
{
#pragma unroll
    for (int kk = 0; kk < 4; kk++) {
        uint32_t bh[2][4], bl[2][4];
#pragma unroll
        for (int tn = 0; tn < 2; tn++) {
            const uint32_t g = (uint32_t)(lane >> 3);
            const uint32_t row = (uint32_t)(nbase + tn * 16) + ((g >> 1) << 3) + (uint32_t)(lane & 7);
            const uint32_t kb = (uint32_t)(kk * 32) + ((g & 1u) << 4);
            const uint32_t off = row * 128u + (kb ^ ((row & 7u) << 4));
            LDSM4(bh[tn], sBh + off);
            LDSM4(bl[tn], sBl + off);
        }
#pragma unroll
        for (int tm = 0; tm < TM; tm++) {
            uint32_t ah[4], al[4];
            const uint32_t row = (uint32_t)(mbase + tm * 16 + (lane & 15));
            const uint32_t kb = (uint32_t)(kk * 32) + ((uint32_t)(lane >> 4) << 4);
            const uint32_t off = row * 128u + (kb ^ ((row & 7u) << 4));
            LDSM4(ah, sAh + off);
            LDSM4(al, sAl + off);
#pragma unroll
            for (int tn = 0; tn < 4; tn++)
                MMA(acc[tm][tn], ah, bh[tn >> 1][(tn & 1) * 2], bh[tn >> 1][(tn & 1) * 2 + 1]);
#pragma unroll
            for (int tn = 0; tn < 4; tn++)
                MMA(acc[tm][tn], al, bh[tn >> 1][(tn & 1) * 2], bh[tn >> 1][(tn & 1) * 2 + 1]);
#pragma unroll
            for (int tn = 0; tn < 4; tn++)
                MMA(acc[tm][tn], ah, bl[tn >> 1][(tn & 1) * 2], bl[tn >> 1][(tn & 1) * 2 + 1]);
        }
    }
}

template <int TM>
__device__ __forceinline__ void store_acc(float* sacc, int pitch, float acc[TM][4][4],
                                          int mbase, int nbase, int lane) {
#pragma unroll
    for (int tm = 0; tm < TM; tm++)
#pragma unroll
        for (int tn = 0; tn < 4; tn++) {
            const int r = mbase + tm * 16 + (lane >> 2);
            const int cc = nbase + tn * 8 + (lane & 3) * 2;
            *(float2*)&sacc[r * pitch + cc] = make_float2(acc[tm][tn][0], acc[tm][tn][1]);
            *(float2*)&sacc[(r + 8) * pitch + cc] = make_float2(acc[tm][tn][2], acc[tm][tn][3]);
        }
}

// ---------------- prep kernels (pre-swizzled chunk-major images) ----------------
__global__ void init_kernel() {
    int i = blockIdx.x * blockDim.x + threadIdx.x;
    if (i < BB * HH) {
        g_hp[0][0][i] = __float2bfloat16(0.f);
        g_hp[0][1][i] = __float2bfloat16(0.f);
        g_c[i] = 0.f;
    }
}

__global__ void prep_w(const float* __restrict__ Whh) {
    size_t i = (size_t)blockIdx.x * 256 + threadIdx.x;
    if (i >= (size_t)G4 * HH) return;
    int n = (int)(i / HH), k = (int)(i % HH);
    int gc = (n & 3) * HH + (n >> 2);
    float w = Whh[(size_t)gc * HH + k];
    __nv_bfloat16 hi = __float2bfloat16(w);
    int ck = k >> 6, col = k & 63;
    int unit = (col >> 3) ^ (n & 7);
    size_t oi = ((size_t)ck * G4 + n) * 64 + unit * 8 + (col & 7);
    g_wpk[0][oi] = hi;
    g_wpk[1][oi] = __float2bfloat16(w - __bfloat162float(hi));
}

__global__ void prep_wi(const float* __restrict__ Wih, const float* __restrict__ bih,
                        const float* __restrict__ bhh) {
    size_t i = (size_t)blockIdx.x * 256 + threadIdx.x;
    if (i >= (size_t)G4 * XP) return;
    int n = (int)(i / XP), k = (int)(i % XP);
    int gc = (n & 3) * HH + (n >> 2);
    float w = (k < DD) ? Wih[(size_t)gc * DD + k] : 0.f;
    __nv_bfloat16 hi = __float2bfloat16(w);
    int ck = k >> 6, col = k & 63;
    int unit = (col >> 3) ^ (n & 7);
    size_t oi = ((size_t)ck * G4 + n) * 64 + unit * 8 + (col & 7);
    g_wipk[0][oi] = hi;
    g_wipk[1][oi] = __float2bfloat16(w - __bfloat162float(hi));
    if (k == 0) g_bsum[n] = bih[gc] + bhh[gc];
}

__global__ void prep_x(const float* __restrict__ xt, const float* __restrict__ xa,
                       const float* __restrict__ xv) {
    size_t i = (size_t)blockIdx.x * 256 + threadIdx.x;
    if (i >= (size_t)TT * BB * XP) return;
    int d = (int)(i % XP);
    size_t tb = i / XP;
    int b = (int)(tb % BB), t = (int)(tb / BB);
    float v = 0.f;
    if (d < D_TXT)              v = xt[((size_t)b * TT + t) * D_TXT + d];
    else if (d < D_TXT + D_AUD) v = xa[((size_t)b * TT + t) * D_AUD + (d - D_TXT)];
    else if (d < DD)            v = xv[((size_t)b * TT + t) * D_VIS + (d - D_TXT - D_AUD)];
    __nv_bfloat16 hi = __float2bfloat16(v);
    int ck = d >> 6, col = d & 63;
    int unit = (col >> 3) ^ (b & 7);
    size_t oi = (((size_t)t * 7 + ck) * BB + b) * 64 + unit * 8 + (col & 7);
    g_xpk[0][oi] = hi;
    g_xpk[1][oi] = __float2bfloat16(v - __bfloat162float(hi));
}

// ---------------- xg GEMM: xg = x @ Wih^T + bias ----------------
// 128x128 tiles, grid (32, 512). 7 chunks, 3 stages x 64KB (Ah|Al|Bh|Bl).
// 288 threads: warps 0-7 compute, thread 256 = producer.
#define XG_PITCH 132
#define XG_STAGE 65536u
__global__ __launch_bounds__(288, 1) void xg_kernel() {
    extern __shared__ __align__(128) char dsm[];
    __shared__ __align__(8) uint64_t s_full[3], s_empty[3];
    const int tid = threadIdx.x;
    const int lane = tid & 31, wid = tid >> 5;
    const int r0 = blockIdx.y * 128, n0 = blockIdx.x * 128;
    const int t = blockIdx.y >> 1, b0 = (blockIdx.y & 1) * 128;
    const uint32_t sb = s2u(dsm);
    const uint32_t fmb = s2u(s_full), emb = s2u(s_empty);

    if (tid == 0)
        for (int s = 0; s < 3; s++) { MBINIT(fmb + s * 8, 1); MBINIT(emb + s * 8, 256); }
    __syncthreads();

    if (tid >= 256) {
        if (tid == 256) {
            for (int ck = 0; ck < 7; ck++) {
                const int s = ck % 3;
                if (ck >= 3) MBWAIT(emb + s * 8, ((ck / 3) - 1) & 1);
                const uint32_t st = sb + (uint32_t)s * XG_STAGE;
                const uint32_t bar = fmb + s * 8;
                MBEXPECT(bar, 65536u);
                BULK(st,          &g_xpk[0][(((size_t)t * 7 + ck) * BB + b0) * 64], 16384u, bar);
                BULK(st + 16384u, &g_xpk[1][(((size_t)t * 7 + ck) * BB + b0) * 64], 16384u, bar);
                BULK(st + 32768u, &g_wipk[0][((size_t)ck * G4 + n0) * 64],          16384u, bar);
                BULK(st + 49152u, &g_wipk[1][((size_t)ck * G4 + n0) * 64],          16384u, bar);
            }
        }
        return;
    }

    const int wy = wid >> 2, wx = wid & 3;
    float acc[4][4][4];
#pragma unroll
    for (int i = 0; i < 4; i++)
#pragma unroll
        for (int j = 0; j < 4; j++)
#pragma unroll
            for (int k = 0; k < 4; k++) acc[i][j][k] = 0.f;

#pragma unroll 1
    for (int ck = 0; ck < 7; ck++) {
        const int s = ck % 3;
        MBWAIT(fmb + s * 8, (ck / 3) & 1);
        const uint32_t st = sb + (uint32_t)s * XG_STAGE;
        fused3_chunk<4>(st, st + 16384u, st + 32768u, st + 49152u,
                        wy * 64, wx * 32, lane, acc);
        MBARRIVE(emb + s * 8);
    }

    BARC();
    float* sacc = (float*)dsm;
    store_acc<4>(sacc, XG_PITCH, acc, wy * 64, wx * 32, lane);
    BARC();
    for (int e = tid; e < 128 * 32; e += 256) {
        const int m = e >> 5, q = e & 31;
        float4 g = *(float4*)&sacc[m * XG_PITCH + q * 4];
        const float4 bs = *(const float4*)&g_bsum[n0 + q * 4];
        g.x += bs.x; g.y += bs.y; g.z += bs.z; g.w += bs.w;
        *(float4*)&g_xg[(size_t)(r0 + m) * G4 + n0 + q * 4] = g;
    }
}

// ---------------- LSTM step: gates = h @ Whh^T + xg; cell update ----------------
// 128(m) x 64(n) tiles, grid (64, 2) = 128 CTAs. 16 chunks, 4 stages x 48KB.
// 288 threads: warps 0-7 compute, thread 256 = producer.
#define ST_PITCH 68
#define ST_STAGE 49152u
__global__ __launch_bounds__(288, 1) void step_kernel(int t) {
    extern __shared__ __align__(128) char dsm[];
    __shared__ __align__(8) uint64_t s_full[4], s_empty[4];
    const int tid = threadIdx.x;
    const int lane = tid & 31, wid = tid >> 5;
    const int m0 = blockIdx.y * 128, n0 = blockIdx.x * 64;
    const int rb = t & 1, wb = rb ^ 1;
    const uint32_t sb = s2u(dsm);
    const uint32_t fmb = s2u(s_full), emb = s2u(s_empty);

    if (tid == 0)
        for (int s = 0; s < 4; s++) { MBINIT(fmb + s * 8, 1); MBINIT(emb + s * 8, 256); }
    __syncthreads();

    if (tid >= 256) {
        if (tid == 256) {
            for (int ck = 0; ck < 16; ck++) {
                const int s = ck & 3;
                if (ck >= 4) MBWAIT(emb + s * 8, ((ck >> 2) - 1) & 1);
                const uint32_t st = sb + (uint32_t)s * ST_STAGE;
                const uint32_t bar = fmb + s * 8;
                MBEXPECT(bar, 49152u);
                BULK(st,          &g_hp[rb][0][((size_t)ck * 256 + m0) * 64], 16384u, bar);
                BULK(st + 16384u, &g_hp[rb][1][((size_t)ck * 256 + m0) * 64], 16384u, bar);
                BULK(st + 32768u, &g_wpk[0][((size_t)ck * G4 + n0) * 64],      8192u, bar);
                BULK(st + 40960u, &g_wpk[1][((size_t)ck * G4 + n0) * 64],      8192u, bar);
            }
        }
        return;
    }

    const int wy = wid >> 1, wx = wid & 1;   // warp grid 4(m) x 2(n), warp tile 32x32
    float acc[2][4][4];
#pragma unroll
    for (int i = 0; i < 2; i++)
#pragma unroll
        for (int j = 0; j < 4; j++)
#pragma unroll
            for (int k = 0; k < 4; k++) acc[i][j][k] = 0.f;

#pragma unroll 1
    for (int ck = 0; ck < 16; ck++) {
        const int s = ck & 3;
        MBWAIT(fmb + s * 8, (ck >> 2) & 1);
        const uint32_t st = sb + (uint32_t)s * ST_STAGE;
        fused3_chunk<2>(st, st + 16384u, st + 32768u, st + 40960u,
                        wy * 32, wx * 32, lane, acc);
        MBARRIVE(emb + s * 8);
    }

    BARC();
    float* sacc = (float*)dsm;
    store_acc<2>(sacc, ST_PITCH, acc, wy * 32, wx * 32, lane);
    BARC();

    // cell update: packed n -> j = n>>2, bands i,f,g,o = n&3
    for (int e = tid; e < 128 * 16; e += 256) {
        const int mloc = e >> 4, q = e & 15;
        const int gm = m0 + mloc;
        const float4 g = *(float4*)&sacc[mloc * ST_PITCH + q * 4];
        const float4 xgv = *(const float4*)&g_xg[((size_t)t * BB + gm) * G4 + n0 + q * 4];
        const float gi = g.x + xgv.x;
        const float gf = g.y + xgv.y;
        const float gg = g.z + xgv.z;
        const float go = g.w + xgv.w;
        const float si = 1.f / (1.f + __expf(-gi));
        const float sf = 1.f / (1.f + __expf(-gf));
        const float tg = tanhf(gg);
        const float so = 1.f / (1.f + __expf(-go));
        const int j = (n0 >> 2) + q;
        const size_t cidx = (size_t)gm * HH + j;
        const float c = sf * g_c[cidx] + si * tg;
        g_c[cidx] = c;
        const float h = so * tanhf(c);
        const __nv_bfloat16 hh = __float2bfloat16(h);
        const int ck = j >> 6, col = j & 63;
        const int unit = (col >> 3) ^ (gm & 7);
        const size_t hidx = ((size_t)ck * 256 + gm) * 64 + unit * 8 + (col & 7);
        g_hp[wb][0][hidx] = hh;
        g_hp[wb][1][hidx] = __float2bfloat16(h - __bfloat162float(hh));
        if (t == TT - 1) g_hf[cidx] = h;
    }
}

// ---------------- MLP head ----------------
__global__ __launch_bounds__(256) void mlp_kernel(
    const float* __restrict__ W1, const float* __restrict__ b1,
    const float* __restrict__ W2, const float* __restrict__ b2,
    float* __restrict__ out) {
    __shared__ float hrow[HH];
    __shared__ float red[256];
    const int b = blockIdx.x;
    const int tid = threadIdx.x;

    const float* __restrict__ h = &g_hf[(size_t)b * HH];
    for (int k = tid; k < HH; k += 256) hrow[k] = h[k];
    __syncthreads();

    float sum = 0.f;
    for (int cc = tid; cc < NCELL; cc += 256) {
        const float* __restrict__ w = &W1[(size_t)cc * HH];
        float acc = b1[cc];
        for (int k = 0; k < HH; k += 4) {
            const float4 wv = *(const float4*)&w[k];
            acc += hrow[k] * wv.x + hrow[k + 1] * wv.y + hrow[k + 2] * wv.z + hrow[k + 3] * wv.w;
        }
        sum += fmaxf(acc, 0.f) * W2[cc];
    }
    red[tid] = sum;
    __syncthreads();
    for (int s = 128; s > 0; s >>= 1) {
        if (tid < s) red[tid] += red[tid + s];
        __syncthreads();
    }
    if (tid == 0) out[b] = red[0] + b2[0];
}

// ---------------- launch ----------------
extern "C" void kernel_launch(void* const* d_in, const int* in_sizes, int n_in,
                              void* d_out, int out_size) {
    const float* xt  = (const float*)d_in[0];
    const float* xa  = (const float*)d_in[1];
    const float* xv  = (const float*)d_in[2];
    const float* Wih = (const float*)d_in[3];
    const float* Whh = (const float*)d_in[4];
    const float* bih = (const float*)d_in[5];
    const float* bhh = (const float*)d_in[6];
    const float* W1  = (const float*)d_in[7];
    const float* b1  = (const float*)d_in[8];
    const float* W2  = (const float*)d_in[9];
    const float* b2  = (const float*)d_in[10];
    float* out = (float*)d_out;

    const int DSM_XG = 3 * 65536;   // 192KB
    const int DSM_ST = 4 * 49152;   // 192KB
    cudaFuncSetAttribute(xg_kernel, cudaFuncAttributeMaxDynamicSharedMemorySize, DSM_XG);
    cudaFuncSetAttribute(step_kernel, cudaFuncAttributeMaxDynamicSharedMemorySize, DSM_ST);

    init_kernel<<<(BB * HH + 255) / 256, 256>>>();
    prep_w<<<(int)(((size_t)G4 * HH + 255) / 256), 256>>>(Whh);
    prep_wi<<<(int)(((size_t)G4 * XP + 255) / 256), 256>>>(Wih, bih, bhh);
    prep_x<<<(int)(((size_t)TT * BB * XP + 255) / 256), 256>>>(xt, xa, xv);
    xg_kernel<<<dim3(32, 512), 288, DSM_XG>>>();
    for (int t = 0; t < TT; t++)
        step_kernel<<<dim3(64, 2), 288, DSM_ST>>>(t);
    mlp_kernel<<<BB, 256>>>(W1, b1, W2, b2, out);
}

// round 10
// speedup vs baseline: 3.0301x; 1.1507x over previous
#include <cuda_runtime.h>
#include <cuda_bf16.h>
#include <cstdint>

// EFLSTM via warp-level bf16 mma.sync + cp.async.bulk staging + warp-specialized producer.
//   phase 1: xg = x @ Wih^T + bias  (parallel GEMM, bf16x3 = Ah*Bh+Al*Bh+Ah*Bl, fp32 out)
//   phase 2: 256 sequential steps: gates = h @ Whh^T + xg  (bf16x2: h hi/lo pair x W-hi)
//   phase 3: MLP head
// Packed gmem layouts chunk-major, PRE-SWIZZLED (exact smem image), one bulk copy per tile.
// Gate cols permuted n = j*4 + band so the cell update is CTA-local.

#define BB 256
#define TT 256
#define D_TXT 300
#define D_AUD 74
#define D_VIS 35
#define DD 409
#define HH 1024
#define G4 4096
#define XP 448
#define NCELL 512

// ---------------- device scratch ----------------
__device__ __nv_bfloat16 g_hp[2][2][16 * 256 * 64];          // h images [buf][hi/lo]
__device__ float g_c[BB * HH];
__device__ float g_hf[BB * HH];
__device__ __nv_bfloat16 g_wpk[(size_t)16 * G4 * 64];        // Whh image (hi only)
__device__ __nv_bfloat16 g_wipk[2][(size_t)7 * G4 * 64];     // Wih images hi/lo
__device__ __nv_bfloat16 g_xpk[2][(size_t)TT * 7 * BB * 64]; // x images hi/lo
__device__ float g_bsum[G4];
__device__ float g_xg[(size_t)TT * BB * G4];

// ---------------- helpers ----------------
__device__ __forceinline__ uint32_t s2u(const void* p) {
    uint32_t a;
    asm("{ .reg .u64 t; cvta.to.shared.u64 t, %1; cvt.u32.u64 %0, t; }" : "=r"(a) : "l"(p));
    return a;
}
#define MBINIT(a, c) asm volatile("mbarrier.init.shared.b64 [%0], %1;" ::"r"(a), "r"(c) : "memory")
#define MBARRIVE(a) asm volatile("mbarrier.arrive.shared.b64 _, [%0];" ::"r"(a) : "memory")
#define MBWAIT(a, ph) do {                                                                  \
    uint32_t _d;                                                                            \
    asm volatile("{\n .reg .pred p;\n mbarrier.try_wait.parity.acquire.cta.shared::cta.b64 p,[%1],%2;\n selp.b32 %0,1,0,p;\n}" \
                 : "=r"(_d) : "r"(a), "r"(ph) : "memory");                                  \
    while (!_d) {                                                                           \
        asm volatile("{\n .reg .pred p;\n mbarrier.try_wait.parity.acquire.cta.shared::cta.b64 p,[%1],%2,0x989680;\n selp.b32 %0,1,0,p;\n}" \
                     : "=r"(_d) : "r"(a), "r"(ph) : "memory");                              \
    }                                                                                       \
} while (0)
#define MBEXPECT(bar, bytes) \
    asm volatile("mbarrier.arrive.expect_tx.shared.b64 _, [%0], %1;" ::"r"(bar), "r"(bytes) : "memory")
#define BULK(dst, src, bytes, bar)                                                          \
    asm volatile("cp.async.bulk.shared::cluster.global.mbarrier::complete_tx::bytes "       \
                 "[%0], [%1], %2, [%3];"                                                    \
                 ::"r"(dst), "l"((const void*)(src)), "r"(bytes), "r"(bar) : "memory")
#define BARC() asm volatile("bar.sync 1, 256;" ::: "memory")
#define LDSM4(r, a)                                                                         \
    asm volatile("ldmatrix.sync.aligned.m8n8.x4.shared.b16 {%0,%1,%2,%3}, [%4];"            \
                 : "=r"((r)[0]), "=r"((r)[1]), "=r"((r)[2]), "=r"((r)[3]) : "r"(a))
#define MMA(acc, a, b0, b1)                                                                 \
    asm volatile("mma.sync.aligned.m16n8k16.row.col.f32.bf16.bf16.f32 "                     \
                 "{%0,%1,%2,%3}, {%4,%5,%6,%7}, {%8,%9}, {%0,%1,%2,%3};"                    \
                 : "+f"((acc)[0]), "+f"((acc)[1]), "+f"((acc)[2]), "+f"((acc)[3])           \
                 : "r"((a)[0]), "r"((a)[1]), "r"((a)[2]), "r"((a)[3]), "r"(b0), "r"(b1))

// 3-term chunk (xg): Ah*Bh + Al*Bh + Ah*Bl. Warp tile (TM*16) x 32.
template <int TM>
__device__ __forceinline__ void fused3_chunk(
    uint32_t sAh, uint32_t sAl, uint32_t sBh, uint32_t sBl,
    int mbase, int nbase, int lane, float acc[TM][4][4])
{
#pragma unroll
    for (int kk = 0; kk < 4; kk++) {
        uint32_t bh[2][4], bl[2][4];
#pragma unroll
        for (int tn = 0; tn < 2; tn++) {
            const uint32_t g = (uint32_t)(lane >> 3);
            const uint32_t row = (uint32_t)(nbase + tn * 16) + ((g >> 1) << 3) + (uint32_t)(lane & 7);
            const uint32_t kb = (uint32_t)(kk * 32) + ((g & 1u) << 4);
            const uint32_t off = row * 128u + (kb ^ ((row & 7u) << 4));
            LDSM4(bh[tn], sBh + off);
            LDSM4(bl[tn], sBl + off);
        }
#pragma unroll
        for (int tm = 0; tm < TM; tm++) {
            uint32_t ah[4], al[4];
            const uint32_t row = (uint32_t)(mbase + tm * 16 + (lane & 15));
            const uint32_t kb = (uint32_t)(kk * 32) + ((uint32_t)(lane >> 4) << 4);
            const uint32_t off = row * 128u + (kb ^ ((row & 7u) << 4));
            LDSM4(ah, sAh + off);
            LDSM4(al, sAl + off);
#pragma unroll
            for (int tn = 0; tn < 4; tn++)
                MMA(acc[tm][tn], ah, bh[tn >> 1][(tn & 1) * 2], bh[tn >> 1][(tn & 1) * 2 + 1]);
#pragma unroll
            for (int tn = 0; tn < 4; tn++)
                MMA(acc[tm][tn], al, bh[tn >> 1][(tn & 1) * 2], bh[tn >> 1][(tn & 1) * 2 + 1]);
#pragma unroll
            for (int tn = 0; tn < 4; tn++)
                MMA(acc[tm][tn], ah, bl[tn >> 1][(tn & 1) * 2], bl[tn >> 1][(tn & 1) * 2 + 1]);
        }
    }
}

// 2-term chunk (recurrence): (Ah + Al) * Bh. Warp tile (TM*16) x 32.
template <int TM>
__device__ __forceinline__ void fused2_chunk(
    uint32_t sAh, uint32_t sAl, uint32_t sBh,
    int mbase, int nbase, int lane, float acc[TM][4][4])
{
#pragma unroll
    for (int kk = 0; kk < 4; kk++) {
        uint32_t bh[2][4];
#pragma unroll
        for (int tn = 0; tn < 2; tn++) {
            const uint32_t g = (uint32_t)(lane >> 3);
            const uint32_t row = (uint32_t)(nbase + tn * 16) + ((g >> 1) << 3) + (uint32_t)(lane & 7);
            const uint32_t kb = (uint32_t)(kk * 32) + ((g & 1u) << 4);
            const uint32_t off = row * 128u + (kb ^ ((row & 7u) << 4));
            LDSM4(bh[tn], sBh + off);
        }
#pragma unroll
        for (int tm = 0; tm < TM; tm++) {
            uint32_t ah[4], al[4];
            const uint32_t row = (uint32_t)(mbase + tm * 16 + (lane & 15));
            const uint32_t kb = (uint32_t)(kk * 32) + ((uint32_t)(lane >> 4) << 4);
            const uint32_t off = row * 128u + (kb ^ ((row & 7u) << 4));
            LDSM4(ah, sAh + off);
            LDSM4(al, sAl + off);
#pragma unroll
            for (int tn = 0; tn < 4; tn++)
                MMA(acc[tm][tn], ah, bh[tn >> 1][(tn & 1) * 2], bh[tn >> 1][(tn & 1) * 2 + 1]);
#pragma unroll
            for (int tn = 0; tn < 4; tn++)
                MMA(acc[tm][tn], al, bh[tn >> 1][(tn & 1) * 2], bh[tn >> 1][(tn & 1) * 2 + 1]);
        }
    }
}

template <int TM>
__device__ __forceinline__ void store_acc(float* sacc, int pitch, float acc[TM][4][4],
                                          int mbase, int nbase, int lane) {
#pragma unroll
    for (int tm = 0; tm < TM; tm++)
#pragma unroll
        for (int tn = 0; tn < 4; tn++) {
            const int r = mbase + tm * 16 + (lane >> 2);
            const int cc = nbase + tn * 8 + (lane & 3) * 2;
            *(float2*)&sacc[r * pitch + cc] = make_float2(acc[tm][tn][0], acc[tm][tn][1]);
            *(float2*)&sacc[(r + 8) * pitch + cc] = make_float2(acc[tm][tn][2], acc[tm][tn][3]);
        }
}

// ---------------- prep kernels (pre-swizzled chunk-major images) ----------------
__global__ void init_kernel() {
    int i = blockIdx.x * blockDim.x + threadIdx.x;
    if (i < BB * HH) {
        g_hp[0][0][i] = __float2bfloat16(0.f);
        g_hp[0][1][i] = __float2bfloat16(0.f);
        g_c[i] = 0.f;
    }
}

__global__ void prep_w(const float* __restrict__ Whh) {
    size_t i = (size_t)blockIdx.x * 256 + threadIdx.x;
    if (i >= (size_t)G4 * HH) return;
    int n = (int)(i / HH), k = (int)(i % HH);
    int gc = (n & 3) * HH + (n >> 2);
    float w = Whh[(size_t)gc * HH + k];
    int ck = k >> 6, col = k & 63;
    int unit = (col >> 3) ^ (n & 7);
    g_wpk[((size_t)ck * G4 + n) * 64 + unit * 8 + (col & 7)] = __float2bfloat16(w);
}

__global__ void prep_wi(const float* __restrict__ Wih, const float* __restrict__ bih,
                        const float* __restrict__ bhh) {
    size_t i = (size_t)blockIdx.x * 256 + threadIdx.x;
    if (i >= (size_t)G4 * XP) return;
    int n = (int)(i / XP), k = (int)(i % XP);
    int gc = (n & 3) * HH + (n >> 2);
    float w = (k < DD) ? Wih[(size_t)gc * DD + k] : 0.f;
    __nv_bfloat16 hi = __float2bfloat16(w);
    int ck = k >> 6, col = k & 63;
    int unit = (col >> 3) ^ (n & 7);
    size_t oi = ((size_t)ck * G4 + n) * 64 + unit * 8 + (col & 7);
    g_wipk[0][oi] = hi;
    g_wipk[1][oi] = __float2bfloat16(w - __bfloat162float(hi));
    if (k == 0) g_bsum[n] = bih[gc] + bhh[gc];
}

__global__ void prep_x(const float* __restrict__ xt, const float* __restrict__ xa,
                       const float* __restrict__ xv) {
    size_t i = (size_t)blockIdx.x * 256 + threadIdx.x;
    if (i >= (size_t)TT * BB * XP) return;
    int d = (int)(i % XP);
    size_t tb = i / XP;
    int b = (int)(tb % BB), t = (int)(tb / BB);
    float v = 0.f;
    if (d < D_TXT)              v = xt[((size_t)b * TT + t) * D_TXT + d];
    else if (d < D_TXT + D_AUD) v = xa[((size_t)b * TT + t) * D_AUD + (d - D_TXT)];
    else if (d < DD)            v = xv[((size_t)b * TT + t) * D_VIS + (d - D_TXT - D_AUD)];
    __nv_bfloat16 hi = __float2bfloat16(v);
    int ck = d >> 6, col = d & 63;
    int unit = (col >> 3) ^ (b & 7);
    size_t oi = (((size_t)t * 7 + ck) * BB + b) * 64 + unit * 8 + (col & 7);
    g_xpk[0][oi] = hi;
    g_xpk[1][oi] = __float2bfloat16(v - __bfloat162float(hi));
}

// ---------------- xg GEMM: xg = x @ Wih^T + bias (3-term) ----------------
// 128x128 tiles, grid (32, 512). 7 chunks, 3 stages x 64KB (Ah|Al|Bh|Bl).
#define XG_PITCH 132
#define XG_STAGE 65536u
__global__ __launch_bounds__(288, 1) void xg_kernel() {
    extern __shared__ __align__(128) char dsm[];
    __shared__ __align__(8) uint64_t s_full[3], s_empty[3];
    const int tid = threadIdx.x;
    const int lane = tid & 31, wid = tid >> 5;
    const int r0 = blockIdx.y * 128, n0 = blockIdx.x * 128;
    const int t = blockIdx.y >> 1, b0 = (blockIdx.y & 1) * 128;
    const uint32_t sb = s2u(dsm);
    const uint32_t fmb = s2u(s_full), emb = s2u(s_empty);

    if (tid == 0)
        for (int s = 0; s < 3; s++) { MBINIT(fmb + s * 8, 1); MBINIT(emb + s * 8, 256); }
    __syncthreads();

    if (tid >= 256) {
        if (tid == 256) {
            for (int ck = 0; ck < 7; ck++) {
                const int s = ck % 3;
                if (ck >= 3) MBWAIT(emb + s * 8, ((ck / 3) - 1) & 1);
                const uint32_t st = sb + (uint32_t)s * XG_STAGE;
                const uint32_t bar = fmb + s * 8;
                MBEXPECT(bar, 65536u);
                BULK(st,          &g_xpk[0][(((size_t)t * 7 + ck) * BB + b0) * 64], 16384u, bar);
                BULK(st + 16384u, &g_xpk[1][(((size_t)t * 7 + ck) * BB + b0) * 64], 16384u, bar);
                BULK(st + 32768u, &g_wipk[0][((size_t)ck * G4 + n0) * 64],          16384u, bar);
                BULK(st + 49152u, &g_wipk[1][((size_t)ck * G4 + n0) * 64],          16384u, bar);
            }
        }
        return;
    }

    const int wy = wid >> 2, wx = wid & 3;
    float acc[4][4][4];
#pragma unroll
    for (int i = 0; i < 4; i++)
#pragma unroll
        for (int j = 0; j < 4; j++)
#pragma unroll
            for (int k = 0; k < 4; k++) acc[i][j][k] = 0.f;

#pragma unroll 1
    for (int ck = 0; ck < 7; ck++) {
        const int s = ck % 3;
        MBWAIT(fmb + s * 8, (ck / 3) & 1);
        const uint32_t st = sb + (uint32_t)s * XG_STAGE;
        fused3_chunk<4>(st, st + 16384u, st + 32768u, st + 49152u,
                        wy * 64, wx * 32, lane, acc);
        MBARRIVE(emb + s * 8);
    }

    BARC();
    float* sacc = (float*)dsm;
    store_acc<4>(sacc, XG_PITCH, acc, wy * 64, wx * 32, lane);
    BARC();
    for (int e = tid; e < 128 * 32; e += 256) {
        const int m = e >> 5, q = e & 31;
        float4 g = *(float4*)&sacc[m * XG_PITCH + q * 4];
        const float4 bs = *(const float4*)&g_bsum[n0 + q * 4];
        g.x += bs.x; g.y += bs.y; g.z += bs.z; g.w += bs.w;
        *(float4*)&g_xg[(size_t)(r0 + m) * G4 + n0 + q * 4] = g;
    }
}

// ---------------- LSTM step: gates = h @ Whh^T + xg (2-term); cell update ----------
// 128(m) x 64(n) tiles, grid (64, 2) = 128 CTAs. 16 chunks, 4 stages x 40KB.
#define ST_PITCH 68
#define ST_STAGE 40960u
__global__ __launch_bounds__(288, 1) void step_kernel(int t) {
    extern __shared__ __align__(128) char dsm[];
    __shared__ __align__(8) uint64_t s_full[4], s_empty[4];
    const int tid = threadIdx.x;
    const int lane = tid & 31, wid = tid >> 5;
    const int m0 = blockIdx.y * 128, n0 = blockIdx.x * 64;
    const int rb = t & 1, wb = rb ^ 1;
    const uint32_t sb = s2u(dsm);
    const uint32_t fmb = s2u(s_full), emb = s2u(s_empty);

    if (tid == 0)
        for (int s = 0; s < 4; s++) { MBINIT(fmb + s * 8, 1); MBINIT(emb + s * 8, 256); }
    __syncthreads();

    if (tid >= 256) {
        if (tid == 256) {
            for (int ck = 0; ck < 16; ck++) {
                const int s = ck & 3;
                if (ck >= 4) MBWAIT(emb + s * 8, ((ck >> 2) - 1) & 1);
                const uint32_t st = sb + (uint32_t)s * ST_STAGE;
                const uint32_t bar = fmb + s * 8;
                MBEXPECT(bar, 40960u);
                BULK(st,          &g_hp[rb][0][((size_t)ck * 256 + m0) * 64], 16384u, bar);
                BULK(st + 16384u, &g_hp[rb][1][((size_t)ck * 256 + m0) * 64], 16384u, bar);
                BULK(st + 32768u, &g_wpk[((size_t)ck * G4 + n0) * 64],         8192u, bar);
            }
        }
        return;
    }

    const int wy = wid >> 1, wx = wid & 1;   // warp grid 4(m) x 2(n), warp tile 32x32
    float acc[2][4][4];
#pragma unroll
    for (int i = 0; i < 2; i++)
#pragma unroll
        for (int j = 0; j < 4; j++)
#pragma unroll
            for (int k = 0; k < 4; k++) acc[i][j][k] = 0.f;

#pragma unroll 1
    for (int ck = 0; ck < 16; ck++) {
        const int s = ck & 3;
        MBWAIT(fmb + s * 8, (ck >> 2) & 1);
        const uint32_t st = sb + (uint32_t)s * ST_STAGE;
        fused2_chunk<2>(st, st + 16384u, st + 32768u,
                        wy * 32, wx * 32, lane, acc);
        MBARRIVE(emb + s * 8);
    }

    BARC();
    float* sacc = (float*)dsm;
    store_acc<2>(sacc, ST_PITCH, acc, wy * 32, wx * 32, lane);
    BARC();

    // cell update: packed n -> j = n>>2, bands i,f,g,o = n&3
    for (int e = tid; e < 128 * 16; e += 256) {
        const int mloc = e >> 4, q = e & 15;
        const int gm = m0 + mloc;
        const float4 g = *(float4*)&sacc[mloc * ST_PITCH + q * 4];
        const float4 xgv = *(const float4*)&g_xg[((size_t)t * BB + gm) * G4 + n0 + q * 4];
        const float gi = g.x + xgv.x;
        const float gf = g.y + xgv.y;
        const float gg = g.z + xgv.z;
        const float go = g.w + xgv.w;
        const float si = 1.f / (1.f + __expf(-gi));
        const float sf = 1.f / (1.f + __expf(-gf));
        const float tg = tanhf(gg);
        const float so = 1.f / (1.f + __expf(-go));
        const int j = (n0 >> 2) + q;
        const size_t cidx = (size_t)gm * HH + j;
        const float c = sf * g_c[cidx] + si * tg;
        g_c[cidx] = c;
        const float h = so * tanhf(c);
        const __nv_bfloat16 hh = __float2bfloat16(h);
        const int ck = j >> 6, col = j & 63;
        const int unit = (col >> 3) ^ (gm & 7);
        const size_t hidx = ((size_t)ck * 256 + gm) * 64 + unit * 8 + (col & 7);
        g_hp[wb][0][hidx] = hh;
        g_hp[wb][1][hidx] = __float2bfloat16(h - __bfloat162float(hh));
        if (t == TT - 1) g_hf[cidx] = h;
    }
}

// ---------------- MLP head ----------------
__global__ __launch_bounds__(256) void mlp_kernel(
    const float* __restrict__ W1, const float* __restrict__ b1,
    const float* __restrict__ W2, const float* __restrict__ b2,
    float* __restrict__ out) {
    __shared__ float hrow[HH];
    __shared__ float red[256];
    const int b = blockIdx.x;
    const int tid = threadIdx.x;

    const float* __restrict__ h = &g_hf[(size_t)b * HH];
    for (int k = tid; k < HH; k += 256) hrow[k] = h[k];
    __syncthreads();

    float sum = 0.f;
    for (int cc = tid; cc < NCELL; cc += 256) {
        const float* __restrict__ w = &W1[(size_t)cc * HH];
        float acc = b1[cc];
        for (int k = 0; k < HH; k += 4) {
            const float4 wv = *(const float4*)&w[k];
            acc += hrow[k] * wv.x + hrow[k + 1] * wv.y + hrow[k + 2] * wv.z + hrow[k + 3] * wv.w;
        }
        sum += fmaxf(acc, 0.f) * W2[cc];
    }
    red[tid] = sum;
    __syncthreads();
    for (int s = 128; s > 0; s >>= 1) {
        if (tid < s) red[tid] += red[tid + s];
        __syncthreads();
    }
    if (tid == 0) out[b] = red[0] + b2[0];
}

// ---------------- launch ----------------
extern "C" void kernel_launch(void* const* d_in, const int* in_sizes, int n_in,
                              void* d_out, int out_size) {
    const float* xt  = (const float*)d_in[0];
    const float* xa  = (const float*)d_in[1];
    const float* xv  = (const float*)d_in[2];
    const float* Wih = (const float*)d_in[3];
    const float* Whh = (const float*)d_in[4];
    const float* bih = (const float*)d_in[5];
    const float* bhh = (const float*)d_in[6];
    const float* W1  = (const float*)d_in[7];
    const float* b1  = (const float*)d_in[8];
    const float* W2  = (const float*)d_in[9];
    const float* b2  = (const float*)d_in[10];
    float* out = (float*)d_out;

    const int DSM_XG = 3 * 65536;   // 192KB
    const int DSM_ST = 4 * 40960;   // 160KB
    cudaFuncSetAttribute(xg_kernel, cudaFuncAttributeMaxDynamicSharedMemorySize, DSM_XG);
    cudaFuncSetAttribute(step_kernel, cudaFuncAttributeMaxDynamicSharedMemorySize, DSM_ST);

    init_kernel<<<(BB * HH + 255) / 256, 256>>>();
    prep_w<<<(int)(((size_t)G4 * HH + 255) / 256), 256>>>(Whh);
    prep_wi<<<(int)(((size_t)G4 * XP + 255) / 256), 256>>>(Wih, bih, bhh);
    prep_x<<<(int)(((size_t)TT * BB * XP + 255) / 256), 256>>>(xt, xa, xv);
    xg_kernel<<<dim3(32, 512), 288, DSM_XG>>>();
    for (int t = 0; t < TT; t++)
        step_kernel<<<dim3(64, 2), 288, DSM_ST>>>(t);
    mlp_kernel<<<BB, 256>>>(W1, b1, W2, b2, out);
}

// round 11
// speedup vs baseline: 4.1977x; 1.3853x over previous
#include <cuda_runtime.h>
#include <cuda_fp16.h>
#include <cstdint>

// EFLSTM via warp-level fp16 mma.sync (single term) + cp.async.bulk staging +
// warp-specialized producer. fp16 (10-bit mantissa) quantization error is 8x
// smaller than bf16, so single-term GEMMs stay within the 1e-3 rel_err budget.
//   phase 1: xg = x @ Wih^T + bias  (parallel GEMM, fp32 out, 1GB scratch)
//   phase 2: 256 sequential steps: gates = h @ Whh^T + xg; fused LSTM cell update
//   phase 3: MLP head
// Packed gmem layouts chunk-major, PRE-SWIZZLED (exact smem image), one bulk per tile.
// Gate cols permuted n = j*4 + band so the cell update is CTA-local.

#define BB 256
#define TT 256
#define D_TXT 300
#define D_AUD 74
#define D_VIS 35
#define DD 409
#define HH 1024
#define G4 4096
#define XP 448
#define NCELL 512

// ---------------- device scratch ----------------
__device__ __half g_hp[2][16 * 256 * 64];            // h images [buf], fp16
__device__ float g_c[BB * HH];
__device__ float g_hf[BB * HH];
__device__ __half g_wpk[(size_t)16 * G4 * 64];       // Whh image
__device__ __half g_wipk[(size_t)7 * G4 * 64];       // Wih image
__device__ __half g_xpk[(size_t)TT * 7 * BB * 64];   // x image
__device__ float g_bsum[G4];
__device__ float g_xg[(size_t)TT * BB * G4];

// ---------------- helpers ----------------
__device__ __forceinline__ uint32_t s2u(const void* p) {
    uint32_t a;
    asm("{ .reg .u64 t; cvta.to.shared.u64 t, %1; cvt.u32.u64 %0, t; }" : "=r"(a) : "l"(p));
    return a;
}
#define MBINIT(a, c) asm volatile("mbarrier.init.shared.b64 [%0], %1;" ::"r"(a), "r"(c) : "memory")
#define MBARRIVE(a) asm volatile("mbarrier.arrive.shared.b64 _, [%0];" ::"r"(a) : "memory")
#define MBWAIT(a, ph) do {                                                                  \
    uint32_t _d;                                                                            \
    asm volatile("{\n .reg .pred p;\n mbarrier.try_wait.parity.acquire.cta.shared::cta.b64 p,[%1],%2;\n selp.b32 %0,1,0,p;\n}" \
                 : "=r"(_d) : "r"(a), "r"(ph) : "memory");                                  \
    while (!_d) {                                                                           \
        asm volatile("{\n .reg .pred p;\n mbarrier.try_wait.parity.acquire.cta.shared::cta.b64 p,[%1],%2,0x989680;\n selp.b32 %0,1,0,p;\n}" \
                     : "=r"(_d) : "r"(a), "r"(ph) : "memory");                              \
    }                                                                                       \
} while (0)
#define MBEXPECT(bar, bytes) \
    asm volatile("mbarrier.arrive.expect_tx.shared.b64 _, [%0], %1;" ::"r"(bar), "r"(bytes) : "memory")
#define BULK(dst, src, bytes, bar)                                                          \
    asm volatile("cp.async.bulk.shared::cluster.global.mbarrier::complete_tx::bytes "       \
                 "[%0], [%1], %2, [%3];"                                                    \
                 ::"r"(dst), "l"((const void*)(src)), "r"(bytes), "r"(bar) : "memory")
#define BARC() asm volatile("bar.sync 1, 256;" ::: "memory")
#define LDSM4(r, a)                                                                         \
    asm volatile("ldmatrix.sync.aligned.m8n8.x4.shared.b16 {%0,%1,%2,%3}, [%4];"            \
                 : "=r"((r)[0]), "=r"((r)[1]), "=r"((r)[2]), "=r"((r)[3]) : "r"(a))
#define MMAH(acc, a, b0, b1)                                                                \
    asm volatile("mma.sync.aligned.m16n8k16.row.col.f32.f16.f16.f32 "                       \
                 "{%0,%1,%2,%3}, {%4,%5,%6,%7}, {%8,%9}, {%0,%1,%2,%3};"                    \
                 : "+f"((acc)[0]), "+f"((acc)[1]), "+f"((acc)[2]), "+f"((acc)[3])           \
                 : "r"((a)[0]), "r"((a)[1]), "r"((a)[2]), "r"((a)[3]), "r"(b0), "r"(b1))

// single-term fp16 chunk over K=64. Warp tile (TM*16) x 32.
// smem tiles: row-major [rows][64 fp16], 128B/row, swizzle off ^ ((row&7)<<4).
template <int TM>
__device__ __forceinline__ void fused1_chunk(
    uint32_t sA, uint32_t sB, int mbase, int nbase, int lane, float acc[TM][4][4])
{
#pragma unroll
    for (int kk = 0; kk < 4; kk++) {
        uint32_t b[2][4];
#pragma unroll
        for (int tn = 0; tn < 2; tn++) {
            const uint32_t g = (uint32_t)(lane >> 3);
            const uint32_t row = (uint32_t)(nbase + tn * 16) + ((g >> 1) << 3) + (uint32_t)(lane & 7);
            const uint32_t kb = (uint32_t)(kk * 32) + ((g & 1u) << 4);
            const uint32_t off = row * 128u + (kb ^ ((row & 7u) << 4));
            LDSM4(b[tn], sB + off);
        }
#pragma unroll
        for (int tm = 0; tm < TM; tm++) {
            uint32_t a[4];
            const uint32_t row = (uint32_t)(mbase + tm * 16 + (lane & 15));
            const uint32_t kb = (uint32_t)(kk * 32) + ((uint32_t)(lane >> 4) << 4);
            const uint32_t off = row * 128u + (kb ^ ((row & 7u) << 4));
            LDSM4(a, sA + off);
#pragma unroll
            for (int tn = 0; tn < 4; tn++)
                MMAH(acc[tm][tn], a, b[tn >> 1][(tn & 1) * 2], b[tn >> 1][(tn & 1) * 2 + 1]);
        }
    }
}

template <int TM>
__device__ __forceinline__ void store_acc(float* sacc, int pitch, float acc[TM][4][4],
                                          int mbase, int nbase, int lane) {
#pragma unroll
    for (int tm = 0; tm < TM; tm++)
#pragma unroll
        for (int tn = 0; tn < 4; tn++) {
            const int r = mbase + tm * 16 + (lane >> 2);
            const int cc = nbase + tn * 8 + (lane & 3) * 2;
            *(float2*)&sacc[r * pitch + cc] = make_float2(acc[tm][tn][0], acc[tm][tn][1]);
            *(float2*)&sacc[(r + 8) * pitch + cc] = make_float2(acc[tm][tn][2], acc[tm][tn][3]);
        }
}

// ---------------- prep kernels (pre-swizzled chunk-major fp16 images) ----------------
__global__ void init_kernel() {
    int i = blockIdx.x * blockDim.x + threadIdx.x;
    if (i < BB * HH) {
        g_hp[0][i] = __float2half(0.f);
        g_c[i] = 0.f;
    }
}

__global__ void prep_w(const float* __restrict__ Whh) {
    size_t i = (size_t)blockIdx.x * 256 + threadIdx.x;
    if (i >= (size_t)G4 * HH) return;
    int n = (int)(i / HH), k = (int)(i % HH);
    int gc = (n & 3) * HH + (n >> 2);
    float w = Whh[(size_t)gc * HH + k];
    int ck = k >> 6, col = k & 63;
    int unit = (col >> 3) ^ (n & 7);
    g_wpk[((size_t)ck * G4 + n) * 64 + unit * 8 + (col & 7)] = __float2half_rn(w);
}

__global__ void prep_wi(const float* __restrict__ Wih, const float* __restrict__ bih,
                        const float* __restrict__ bhh) {
    size_t i = (size_t)blockIdx.x * 256 + threadIdx.x;
    if (i >= (size_t)G4 * XP) return;
    int n = (int)(i / XP), k = (int)(i % XP);
    int gc = (n & 3) * HH + (n >> 2);
    float w = (k < DD) ? Wih[(size_t)gc * DD + k] : 0.f;
    int ck = k >> 6, col = k & 63;
    int unit = (col >> 3) ^ (n & 7);
    g_wipk[((size_t)ck * G4 + n) * 64 + unit * 8 + (col & 7)] = __float2half_rn(w);
    if (k == 0) g_bsum[n] = bih[gc] + bhh[gc];
}

__global__ void prep_x(const float* __restrict__ xt, const float* __restrict__ xa,
                       const float* __restrict__ xv) {
    size_t i = (size_t)blockIdx.x * 256 + threadIdx.x;
    if (i >= (size_t)TT * BB * XP) return;
    int d = (int)(i % XP);
    size_t tb = i / XP;
    int b = (int)(tb % BB), t = (int)(tb / BB);
    float v = 0.f;
    if (d < D_TXT)              v = xt[((size_t)b * TT + t) * D_TXT + d];
    else if (d < D_TXT + D_AUD) v = xa[((size_t)b * TT + t) * D_AUD + (d - D_TXT)];
    else if (d < DD)            v = xv[((size_t)b * TT + t) * D_VIS + (d - D_TXT - D_AUD)];
    int ck = d >> 6, col = d & 63;
    int unit = (col >> 3) ^ (b & 7);
    g_xpk[(((size_t)t * 7 + ck) * BB + b) * 64 + unit * 8 + (col & 7)] = __float2half_rn(v);
}

// ---------------- xg GEMM: xg = x @ Wih^T + bias (fp16, 1 term) ----------------
// 128x128 tiles, grid (32, 512). 7 chunks, 4 stages x 32KB (A|B).
#define XG_PITCH 132
#define XG_STAGE 32768u
__global__ __launch_bounds__(288, 1) void xg_kernel() {
    extern __shared__ __align__(128) char dsm[];
    __shared__ __align__(8) uint64_t s_full[4], s_empty[4];
    const int tid = threadIdx.x;
    const int lane = tid & 31, wid = tid >> 5;
    const int r0 = blockIdx.y * 128, n0 = blockIdx.x * 128;
    const int t = blockIdx.y >> 1, b0 = (blockIdx.y & 1) * 128;
    const uint32_t sb = s2u(dsm);
    const uint32_t fmb = s2u(s_full), emb = s2u(s_empty);

    if (tid == 0)
        for (int s = 0; s < 4; s++) { MBINIT(fmb + s * 8, 1); MBINIT(emb + s * 8, 256); }
    __syncthreads();

    if (tid >= 256) {
        if (tid == 256) {
            for (int ck = 0; ck < 7; ck++) {
                const int s = ck & 3;
                if (ck >= 4) MBWAIT(emb + s * 8, ((ck >> 2) - 1) & 1);
                const uint32_t st = sb + (uint32_t)s * XG_STAGE;
                const uint32_t bar = fmb + s * 8;
                MBEXPECT(bar, 32768u);
                BULK(st,          &g_xpk[(((size_t)t * 7 + ck) * BB + b0) * 64], 16384u, bar);
                BULK(st + 16384u, &g_wipk[((size_t)ck * G4 + n0) * 64],          16384u, bar);
            }
        }
        return;
    }

    const int wy = wid >> 2, wx = wid & 3;
    float acc[4][4][4];
#pragma unroll
    for (int i = 0; i < 4; i++)
#pragma unroll
        for (int j = 0; j < 4; j++)
#pragma unroll
            for (int k = 0; k < 4; k++) acc[i][j][k] = 0.f;

#pragma unroll 1
    for (int ck = 0; ck < 7; ck++) {
        const int s = ck & 3;
        MBWAIT(fmb + s * 8, (ck >> 2) & 1);
        const uint32_t st = sb + (uint32_t)s * XG_STAGE;
        fused1_chunk<4>(st, st + 16384u, wy * 64, wx * 32, lane, acc);
        MBARRIVE(emb + s * 8);
    }

    BARC();
    float* sacc = (float*)dsm;
    store_acc<4>(sacc, XG_PITCH, acc, wy * 64, wx * 32, lane);
    BARC();
    for (int e = tid; e < 128 * 32; e += 256) {
        const int m = e >> 5, q = e & 31;
        float4 g = *(float4*)&sacc[m * XG_PITCH + q * 4];
        const float4 bs = *(const float4*)&g_bsum[n0 + q * 4];
        g.x += bs.x; g.y += bs.y; g.z += bs.z; g.w += bs.w;
        *(float4*)&g_xg[(size_t)(r0 + m) * G4 + n0 + q * 4] = g;
    }
}

// ---------------- LSTM step: gates = h @ Whh^T + xg (fp16, 1 term); cell update ----
// 128(m) x 64(n) tiles, grid (64, 2) = 128 CTAs. 16 chunks, 4 stages x 24KB.
#define ST_PITCH 68
#define ST_STAGE 24576u
__global__ __launch_bounds__(288, 1) void step_kernel(int t) {
    extern __shared__ __align__(128) char dsm[];
    __shared__ __align__(8) uint64_t s_full[4], s_empty[4];
    const int tid = threadIdx.x;
    const int lane = tid & 31, wid = tid >> 5;
    const int m0 = blockIdx.y * 128, n0 = blockIdx.x * 64;
    const int rb = t & 1, wb = rb ^ 1;
    const uint32_t sb = s2u(dsm);
    const uint32_t fmb = s2u(s_full), emb = s2u(s_empty);

    if (tid == 0)
        for (int s = 0; s < 4; s++) { MBINIT(fmb + s * 8, 1); MBINIT(emb + s * 8, 256); }
    __syncthreads();

    if (tid >= 256) {
        if (tid == 256) {
            for (int ck = 0; ck < 16; ck++) {
                const int s = ck & 3;
                if (ck >= 4) MBWAIT(emb + s * 8, ((ck >> 2) - 1) & 1);
                const uint32_t st = sb + (uint32_t)s * ST_STAGE;
                const uint32_t bar = fmb + s * 8;
                MBEXPECT(bar, 24576u);
                BULK(st,          &g_hp[rb][((size_t)ck * 256 + m0) * 64], 16384u, bar);
                BULK(st + 16384u, &g_wpk[((size_t)ck * G4 + n0) * 64],      8192u, bar);
            }
        }
        return;
    }

    const int wy = wid >> 1, wx = wid & 1;   // warp grid 4(m) x 2(n), warp tile 32x32
    float acc[2][4][4];
#pragma unroll
    for (int i = 0; i < 2; i++)
#pragma unroll
        for (int j = 0; j < 4; j++)
#pragma unroll
            for (int k = 0; k < 4; k++) acc[i][j][k] = 0.f;

#pragma unroll 1
    for (int ck = 0; ck < 16; ck++) {
        const int s = ck & 3;
        MBWAIT(fmb + s * 8, (ck >> 2) & 1);
        const uint32_t st = sb + (uint32_t)s * ST_STAGE;
        fused1_chunk<2>(st, st + 16384u, wy * 32, wx * 32, lane, acc);
        MBARRIVE(emb + s * 8);
    }

    BARC();
    float* sacc = (float*)dsm;
    store_acc<2>(sacc, ST_PITCH, acc, wy * 32, wx * 32, lane);
    BARC();

    // cell update: packed n -> j = n>>2, bands i,f,g,o = n&3
    for (int e = tid; e < 128 * 16; e += 256) {
        const int mloc = e >> 4, q = e & 15;
        const int gm = m0 + mloc;
        const float4 g = *(float4*)&sacc[mloc * ST_PITCH + q * 4];
        const float4 xgv = *(const float4*)&g_xg[((size_t)t * BB + gm) * G4 + n0 + q * 4];
        const float gi = g.x + xgv.x;
        const float gf = g.y + xgv.y;
        const float gg = g.z + xgv.z;
        const float go = g.w + xgv.w;
        const float si = 1.f / (1.f + __expf(-gi));
        const float sf = 1.f / (1.f + __expf(-gf));
        const float tg = tanhf(gg);
        const float so = 1.f / (1.f + __expf(-go));
        const int j = (n0 >> 2) + q;
        const size_t cidx = (size_t)gm * HH + j;
        const float c = sf * g_c[cidx] + si * tg;
        g_c[cidx] = c;
        const float h = so * tanhf(c);
        const int ck = j >> 6, col = j & 63;
        const int unit = (col >> 3) ^ (gm & 7);
        g_hp[wb][((size_t)ck * 256 + gm) * 64 + unit * 8 + (col & 7)] = __float2half_rn(h);
        if (t == TT - 1) g_hf[cidx] = h;
    }
}

// ---------------- MLP head ----------------
__global__ __launch_bounds__(256) void mlp_kernel(
    const float* __restrict__ W1, const float* __restrict__ b1,
    const float* __restrict__ W2, const float* __restrict__ b2,
    float* __restrict__ out) {
    __shared__ float hrow[HH];
    __shared__ float red[256];
    const int b = blockIdx.x;
    const int tid = threadIdx.x;

    const float* __restrict__ h = &g_hf[(size_t)b * HH];
    for (int k = tid; k < HH; k += 256) hrow[k] = h[k];
    __syncthreads();

    float sum = 0.f;
    for (int cc = tid; cc < NCELL; cc += 256) {
        const float* __restrict__ w = &W1[(size_t)cc * HH];
        float acc = b1[cc];
        for (int k = 0; k < HH; k += 4) {
            const float4 wv = *(const float4*)&w[k];
            acc += hrow[k] * wv.x + hrow[k + 1] * wv.y + hrow[k + 2] * wv.z + hrow[k + 3] * wv.w;
        }
        sum += fmaxf(acc, 0.f) * W2[cc];
    }
    red[tid] = sum;
    __syncthreads();
    for (int s = 128; s > 0; s >>= 1) {
        if (tid < s) red[tid] += red[tid + s];
        __syncthreads();
    }
    if (tid == 0) out[b] = red[0] + b2[0];
}

// ---------------- launch ----------------
extern "C" void kernel_launch(void* const* d_in, const int* in_sizes, int n_in,
                              void* d_out, int out_size) {
    const float* xt  = (const float*)d_in[0];
    const float* xa  = (const float*)d_in[1];
    const float* xv  = (const float*)d_in[2];
    const float* Wih = (const float*)d_in[3];
    const float* Whh = (const float*)d_in[4];
    const float* bih = (const float*)d_in[5];
    const float* bhh = (const float*)d_in[6];
    const float* W1  = (const float*)d_in[7];
    const float* b1  = (const float*)d_in[8];
    const float* W2  = (const float*)d_in[9];
    const float* b2  = (const float*)d_in[10];
    float* out = (float*)d_out;

    const int DSM_XG = 4 * 32768;   // 128KB
    const int DSM_ST = 4 * 24576;   // 96KB
    cudaFuncSetAttribute(xg_kernel, cudaFuncAttributeMaxDynamicSharedMemorySize, DSM_XG);
    cudaFuncSetAttribute(step_kernel, cudaFuncAttributeMaxDynamicSharedMemorySize, DSM_ST);

    init_kernel<<<(BB * HH + 255) / 256, 256>>>();
    prep_w<<<(int)(((size_t)G4 * HH + 255) / 256), 256>>>(Whh);
    prep_wi<<<(int)(((size_t)G4 * XP + 255) / 256), 256>>>(Wih, bih, bhh);
    prep_x<<<(int)(((size_t)TT * BB * XP + 255) / 256), 256>>>(xt, xa, xv);
    xg_kernel<<<dim3(32, 512), 288, DSM_XG>>>();
    for (int t = 0; t < TT; t++)
        step_kernel<<<dim3(64, 2), 288, DSM_ST>>>(t);
    mlp_kernel<<<BB, 256>>>(W1, b1, W2, b2, out);
}